// round 10
// baseline (speedup 1.0000x reference)
#include <cuda_runtime.h>
#include <cuda_bf16.h>
#include <cuda_fp16.h>

// Problem constants
#define EMBED_DIM   256
#define D4          64          // EMBED_DIM / 4 (float4 chunks per row)
#define BATCH       8192
#define L_NODE      16
#define L_EDGE      15
#define L_TOTAL     47          // 16 + 15 + 16
#define NNZ         8
#define NUM_VAL     10000
#define ROWS_PER_BLOCK 16

// Precomputed positional-encoding table: 16 positions x 256 dims (16 KB).
__device__ float g_pe[L_NODE * EMBED_DIM];

// int8 copy of val_tab (2.5 MB, L2-resident) + per-row dequant scales (40 KB).
__device__ __align__(16) unsigned int g_val_q[NUM_VAL * D4];   // 4 int8 per uint
__device__ float g_row_scale[NUM_VAL];

__device__ __forceinline__ unsigned int quant4(float4 v, float inv) {
    int a = __float2int_rn(v.x * inv);
    int b = __float2int_rn(v.y * inv);
    int c = __float2int_rn(v.z * inv);
    int d = __float2int_rn(v.w * inv);
    a = max(-127, min(127, a)); b = max(-127, min(127, b));
    c = max(-127, min(127, c)); d = max(-127, min(127, d));
    return (unsigned int)(a & 0xff) | ((unsigned int)(b & 0xff) << 8) |
           ((unsigned int)(c & 0xff) << 16) | ((unsigned int)(d & 0xff) << 24);
}

// Single-pass prep: one warp per table row. Warp absmax -> per-row scale ->
// quantize in place. PE table folded in (blocks 0..15, threads 0..127).
__global__ __launch_bounds__(256)
void prep_kernel(const float4* __restrict__ val_tab) {
    const int warp = (blockIdx.x * 256 + threadIdx.x) >> 5;   // row id
    const int lane = threadIdx.x & 31;
    if (warp < NUM_VAL) {
        const float4 a = __ldg(val_tab + warp * D4 + lane);
        const float4 b = __ldg(val_tab + warp * D4 + 32 + lane);
        float m = fmaxf(fmaxf(fmaxf(fabsf(a.x), fabsf(a.y)), fmaxf(fabsf(a.z), fabsf(a.w))),
                        fmaxf(fmaxf(fabsf(b.x), fabsf(b.y)), fmaxf(fabsf(b.z), fabsf(b.w))));
        #pragma unroll
        for (int s = 16; s > 0; s >>= 1)
            m = fmaxf(m, __shfl_xor_sync(0xffffffffu, m, s));
        const float inv = (m > 0.f) ? 127.0f / m : 0.f;
        g_val_q[warp * D4 + lane]      = quant4(a, inv);
        g_val_q[warp * D4 + 32 + lane] = quant4(b, inv);
        if (lane == 0)
            g_row_scale[warp] = m * (1.0f / 127.0f);
    }
    // PE table on the side.
    if (blockIdx.x < L_NODE && threadIdx.x < 128) {
        const int l = blockIdx.x;
        const int j = threadIdx.x;                     // dim pair (2j, 2j+1)
        const float k = 9.210340371976184f / 256.0f;   // ln(10000)/256
        float div = __expf(-(float)(2 * j) * k);
        float s, c;
        sincosf((float)l * div, &s, &c);
        g_pe[l * EMBED_DIM + 2 * j]     = s;
        g_pe[l * EMBED_DIM + 2 * j + 1] = c;
    }
}

__device__ __forceinline__ float4 f4_add(float4 a, float4 b) {
    return make_float4(a.x + b.x, a.y + b.y, a.z + b.z, a.w + b.w);
}

// Accumulate w * dequant4(u). Sign extension via shifts — plain `char` is
// UNSIGNED on aarch64 (R8 bug); never rely on it.
__device__ __forceinline__ void acc_q4(float4& acc, float w, unsigned int u) {
    acc.x += w * (float)((int)(u << 24) >> 24);
    acc.y += w * (float)((int)(u << 16) >> 24);
    acc.z += w * (float)((int)(u <<  8) >> 24);
    acc.w += w * (float)((int) u        >> 24);
}

// 1D grid, y-fastest interleave of the 47 sequence positions.
__global__ __launch_bounds__(256, 8)
void embed_kernel(const int*    __restrict__ node_idx,   // [16, 8192]
                  const int*    __restrict__ edge_idx,   // [15, 8192]
                  const int*    __restrict__ val_idx,    // [16*8192, 8]
                  const float*  __restrict__ val_w,      // [16*8192, 8]
                  const float4* __restrict__ node_tab,   // [128, 64]
                  const float4* __restrict__ edge_tab,   // [32, 64]
                  float4*       __restrict__ out)        // [47, 8192, 64]
{
    const int bid   = blockIdx.x;
    const int l     = bid % L_TOTAL;              // y-fastest interleave
    const int xblk  = bid / L_TOTAL;
    const int col4  = threadIdx.x & 63;           // float4 column within row
    const int lrow  = threadIdx.x >> 6;           // 0..3 local row
    const int bbase = xblk * ROWS_PER_BLOCK;

    int pos, sec;
    if (l < L_NODE)                { sec = 0; pos = l; }
    else if (l < L_NODE + L_EDGE)  { sec = 1; pos = l - L_NODE; }
    else                           { sec = 2; pos = l - (L_NODE + L_EDGE); }

    // PE chunk for this (pos, col4) — broadcast L1/L2 hit.
    const float4 pe = reinterpret_cast<const float4*>(g_pe)[pos * D4 + col4];

    float4* outsec = out + (size_t)l * BATCH * D4;

    if (sec == 0 || sec == 1) {
        const int*    idxrow = (sec == 0 ? node_idx : edge_idx) + pos * BATCH;
        const float4* tab    = (sec == 0 ? node_tab : edge_tab);
        int idx[ROWS_PER_BLOCK / 4];
        #pragma unroll
        for (int rr = 0; rr < ROWS_PER_BLOCK / 4; rr++)
            idx[rr] = __ldg(idxrow + bbase + rr * 4 + lrow);
        #pragma unroll
        for (int rr = 0; rr < ROWS_PER_BLOCK / 4; rr++) {
            const int b = bbase + rr * 4 + lrow;
            float4 v = __ldg(tab + idx[rr] * D4 + col4);
            __stcs(&outsec[(size_t)b * D4 + col4], f4_add(v, pe));
        }
    } else {
        // Val section: int8 gathers (4 B/lane), per-row scale folded into the
        // weight (broadcast loads from a hot 40 KB array — no DRAM cost).
        #pragma unroll
        for (int rr = 0; rr < ROWS_PER_BLOCK / 4; rr++) {
            const int b = bbase + rr * 4 + lrow;
            const int n = pos * BATCH + b;                 // row into sparse mat
            const int4*   ip = (const int4*)  (val_idx + (size_t)n * NNZ);
            const float4* wp = (const float4*)(val_w   + (size_t)n * NNZ);

            float4 acc = pe;
            {
                const int4   ii = __ldg(ip);
                const float4 ww = __ldg(wp);
                const float s0 = __ldg(g_row_scale + ii.x);
                const float s1 = __ldg(g_row_scale + ii.y);
                const float s2 = __ldg(g_row_scale + ii.z);
                const float s3 = __ldg(g_row_scale + ii.w);
                unsigned int u0 = __ldg(g_val_q + (size_t)ii.x * D4 + col4);
                unsigned int u1 = __ldg(g_val_q + (size_t)ii.y * D4 + col4);
                unsigned int u2 = __ldg(g_val_q + (size_t)ii.z * D4 + col4);
                unsigned int u3 = __ldg(g_val_q + (size_t)ii.w * D4 + col4);
                acc_q4(acc, ww.x * s0, u0);
                acc_q4(acc, ww.y * s1, u1);
                acc_q4(acc, ww.z * s2, u2);
                acc_q4(acc, ww.w * s3, u3);
            }
            {
                const int4   ii = __ldg(ip + 1);
                const float4 ww = __ldg(wp + 1);
                const float s0 = __ldg(g_row_scale + ii.x);
                const float s1 = __ldg(g_row_scale + ii.y);
                const float s2 = __ldg(g_row_scale + ii.z);
                const float s3 = __ldg(g_row_scale + ii.w);
                unsigned int u0 = __ldg(g_val_q + (size_t)ii.x * D4 + col4);
                unsigned int u1 = __ldg(g_val_q + (size_t)ii.y * D4 + col4);
                unsigned int u2 = __ldg(g_val_q + (size_t)ii.z * D4 + col4);
                unsigned int u3 = __ldg(g_val_q + (size_t)ii.w * D4 + col4);
                acc_q4(acc, ww.x * s0, u0);
                acc_q4(acc, ww.y * s1, u1);
                acc_q4(acc, ww.z * s2, u2);
                acc_q4(acc, ww.w * s3, u3);
            }
            __stcs(&outsec[(size_t)b * D4 + col4], acc);
        }
    }
}

extern "C" void kernel_launch(void* const* d_in, const int* in_sizes, int n_in,
                              void* d_out, int out_size) {
    const int*   node_idx = (const int*)  d_in[0];   // [16, 8192]
    const int*   edge_idx = (const int*)  d_in[1];   // [15, 8192]
    const int*   val_idx  = (const int*)  d_in[2];   // [131072, 8]
    const float* val_w    = (const float*)d_in[3];   // [131072, 8]
    const float* node_tab = (const float*)d_in[4];   // [128, 256]
    const float* edge_tab = (const float*)d_in[5];   // [32, 256]
    const float* val_tab  = (const float*)d_in[6];   // [10000, 256]
    float* out = (float*)d_out;                      // [47, 8192, 256]

    (void)in_sizes; (void)n_in; (void)out_size;

    // Single-pass per-row quantization + PE table (one launch).
    // 10000 rows, 1 warp each -> 1250 blocks of 8 warps.
    prep_kernel<<<(NUM_VAL + 7) / 8, 256>>>((const float4*)val_tab);

    const int nblocks = (BATCH / ROWS_PER_BLOCK) * L_TOTAL;   // 512 * 47 = 24064
    embed_kernel<<<nblocks, 256>>>(node_idx, edge_idx, val_idx, val_w,
                                   (const float4*)node_tab,
                                   (const float4*)edge_tab,
                                   (float4*)out);
}

// round 11
// speedup vs baseline: 1.0996x; 1.0996x over previous
#include <cuda_runtime.h>
#include <cuda_bf16.h>
#include <cuda_fp16.h>

// Problem constants
#define EMBED_DIM   256
#define D4          64          // EMBED_DIM / 4 (float4 chunks per row)
#define BATCH       8192
#define L_NODE      16
#define L_EDGE      15
#define L_TOTAL     47          // 16 + 15 + 16
#define NNZ         8
#define NUM_VAL     10000
#define ROWS_PER_BLOCK 16

#define CVT_TOTAL   (NUM_VAL * D4)        // 640000 float4 chunks
#define CVT_HALF    (CVT_TOTAL / 2)       // 320000

// Precomputed positional-encoding table: 16 positions x 256 dims (16 KB).
__device__ float g_pe[L_NODE * EMBED_DIM];

// int8 copy of val_tab: 10000 x 256 bytes = 2.5 MB (fully L2-resident).
__device__ __align__(16) unsigned int g_val_q[NUM_VAL * D4];   // 4 int8 per uint

__device__ float g_absmax;        // zero-init; atomicMax is order-independent
__device__ float g_scale;         // absmax / 127

// Prep A: absmax over val_tab. 1250 blocks x 256 thr, 2 float4/thread,
// warp shfl-reduce -> smem reduce -> ONE atomic per block. PE folded in.
__global__ __launch_bounds__(256)
void prep_absmax_kernel(const float4* __restrict__ val_tab) {
    __shared__ float s_max[8];
    const int t = blockIdx.x * 256 + threadIdx.x;
    float m = 0.f;
    if (t < CVT_HALF) {
        float4 v0 = __ldg(val_tab + t);
        float4 v1 = __ldg(val_tab + t + CVT_HALF);
        m = fmaxf(fmaxf(fmaxf(fabsf(v0.x), fabsf(v0.y)), fmaxf(fabsf(v0.z), fabsf(v0.w))),
                  fmaxf(fmaxf(fabsf(v1.x), fabsf(v1.y)), fmaxf(fabsf(v1.z), fabsf(v1.w))));
    }
    #pragma unroll
    for (int s = 16; s > 0; s >>= 1)
        m = fmaxf(m, __shfl_xor_sync(0xffffffffu, m, s));
    if ((threadIdx.x & 31) == 0) s_max[threadIdx.x >> 5] = m;
    __syncthreads();
    if (threadIdx.x < 32) {
        float bm = (threadIdx.x < 8) ? s_max[threadIdx.x] : 0.f;
        #pragma unroll
        for (int s = 4; s > 0; s >>= 1)
            bm = fmaxf(bm, __shfl_xor_sync(0xffffffffu, bm, s));
        if (threadIdx.x == 0)
            atomicMax(reinterpret_cast<int*>(&g_absmax), __float_as_int(bm));
    }
    // PE table: blocks 0..15, threads 0..127.
    if (blockIdx.x < L_NODE && threadIdx.x < 128) {
        const int l = blockIdx.x;
        const int j = threadIdx.x;                     // dim pair (2j, 2j+1)
        const float k = 9.210340371976184f / 256.0f;   // ln(10000)/256
        float div = __expf(-(float)(2 * j) * k);
        float s, c;
        sincosf((float)l * div, &s, &c);
        g_pe[l * EMBED_DIM + 2 * j]     = s;
        g_pe[l * EMBED_DIM + 2 * j + 1] = c;
    }
}

__device__ __forceinline__ unsigned int quant4(float4 v, float inv) {
    int a = __float2int_rn(v.x * inv);
    int b = __float2int_rn(v.y * inv);
    int c = __float2int_rn(v.z * inv);
    int d = __float2int_rn(v.w * inv);
    a = max(-127, min(127, a)); b = max(-127, min(127, b));
    c = max(-127, min(127, c)); d = max(-127, min(127, d));
    return (unsigned int)(a & 0xff) | ((unsigned int)(b & 0xff) << 8) |
           ((unsigned int)(c & 0xff) << 16) | ((unsigned int)(d & 0xff) << 24);
}

// Prep B: quantize val_tab -> int8 with global scale (1250 blocks, MLP 2).
__global__ __launch_bounds__(256)
void prep_quant_kernel(const float4* __restrict__ val_tab) {
    const float amax = g_absmax;
    const float inv  = 127.0f / amax;
    const int t = blockIdx.x * 256 + threadIdx.x;
    if (t < CVT_HALF) {
        float4 v0 = __ldg(val_tab + t);
        float4 v1 = __ldg(val_tab + t + CVT_HALF);
        g_val_q[t]            = quant4(v0, inv);
        g_val_q[t + CVT_HALF] = quant4(v1, inv);
    }
    if (t == 0) g_scale = amax / 127.0f;
}

__device__ __forceinline__ float4 f4_add(float4 a, float4 b) {
    return make_float4(a.x + b.x, a.y + b.y, a.z + b.z, a.w + b.w);
}

// Accumulate w * dequant4(u). Sign extension via shifts — plain `char` is
// UNSIGNED on aarch64 (R8 bug); never rely on it.
__device__ __forceinline__ void acc_q4(float4& acc, float w, unsigned int u) {
    acc.x += w * (float)((int)(u << 24) >> 24);
    acc.y += w * (float)((int)(u << 16) >> 24);
    acc.z += w * (float)((int)(u <<  8) >> 24);
    acc.w += w * (float)((int) u        >> 24);
}

// 1D grid, y-fastest interleave of the 47 sequence positions.
__global__ __launch_bounds__(256, 8)
void embed_kernel(const int*    __restrict__ node_idx,   // [16, 8192]
                  const int*    __restrict__ edge_idx,   // [15, 8192]
                  const int*    __restrict__ val_idx,    // [16*8192, 8]
                  const float*  __restrict__ val_w,      // [16*8192, 8]
                  const float4* __restrict__ node_tab,   // [128, 64]
                  const float4* __restrict__ edge_tab,   // [32, 64]
                  float4*       __restrict__ out)        // [47, 8192, 64]
{
    const int bid   = blockIdx.x;
    const int l     = bid % L_TOTAL;              // y-fastest interleave
    const int xblk  = bid / L_TOTAL;
    const int col4  = threadIdx.x & 63;           // float4 column within row
    const int lrow  = threadIdx.x >> 6;           // 0..3 local row
    const int bbase = xblk * ROWS_PER_BLOCK;

    int pos, sec;
    if (l < L_NODE)                { sec = 0; pos = l; }
    else if (l < L_NODE + L_EDGE)  { sec = 1; pos = l - L_NODE; }
    else                           { sec = 2; pos = l - (L_NODE + L_EDGE); }

    // PE chunk for this (pos, col4) — broadcast L1/L2 hit.
    const float4 pe = reinterpret_cast<const float4*>(g_pe)[pos * D4 + col4];

    float4* outsec = out + (size_t)l * BATCH * D4;

    if (sec == 0 || sec == 1) {
        const int*    idxrow = (sec == 0 ? node_idx : edge_idx) + pos * BATCH;
        const float4* tab    = (sec == 0 ? node_tab : edge_tab);
        int idx[ROWS_PER_BLOCK / 4];
        #pragma unroll
        for (int rr = 0; rr < ROWS_PER_BLOCK / 4; rr++)
            idx[rr] = __ldg(idxrow + bbase + rr * 4 + lrow);
        #pragma unroll
        for (int rr = 0; rr < ROWS_PER_BLOCK / 4; rr++) {
            const int b = bbase + rr * 4 + lrow;
            float4 v = __ldg(tab + idx[rr] * D4 + col4);
            __stcs(&outsec[(size_t)b * D4 + col4], f4_add(v, pe));
        }
    } else {
        const float gs = g_scale;
        // Val section: int8 gathers (4 B/lane -> 1 wavefront/warp), fp32
        // accumulate of w*q, single global-scale multiply at the end.
        #pragma unroll
        for (int rr = 0; rr < ROWS_PER_BLOCK / 4; rr++) {
            const int b = bbase + rr * 4 + lrow;
            const int n = pos * BATCH + b;                 // row into sparse mat
            const int4*   ip = (const int4*)  (val_idx + (size_t)n * NNZ);
            const float4* wp = (const float4*)(val_w   + (size_t)n * NNZ);

            float4 accq = make_float4(0.f, 0.f, 0.f, 0.f);
            {
                const int4   ii = __ldg(ip);
                const float4 ww = __ldg(wp);
                unsigned int u0 = __ldg(g_val_q + (size_t)ii.x * D4 + col4);
                unsigned int u1 = __ldg(g_val_q + (size_t)ii.y * D4 + col4);
                unsigned int u2 = __ldg(g_val_q + (size_t)ii.z * D4 + col4);
                unsigned int u3 = __ldg(g_val_q + (size_t)ii.w * D4 + col4);
                acc_q4(accq, ww.x, u0);
                acc_q4(accq, ww.y, u1);
                acc_q4(accq, ww.z, u2);
                acc_q4(accq, ww.w, u3);
            }
            {
                const int4   ii = __ldg(ip + 1);
                const float4 ww = __ldg(wp + 1);
                unsigned int u0 = __ldg(g_val_q + (size_t)ii.x * D4 + col4);
                unsigned int u1 = __ldg(g_val_q + (size_t)ii.y * D4 + col4);
                unsigned int u2 = __ldg(g_val_q + (size_t)ii.z * D4 + col4);
                unsigned int u3 = __ldg(g_val_q + (size_t)ii.w * D4 + col4);
                acc_q4(accq, ww.x, u0);
                acc_q4(accq, ww.y, u1);
                acc_q4(accq, ww.z, u2);
                acc_q4(accq, ww.w, u3);
            }
            float4 res = make_float4(pe.x + gs * accq.x, pe.y + gs * accq.y,
                                     pe.z + gs * accq.z, pe.w + gs * accq.w);
            __stcs(&outsec[(size_t)b * D4 + col4], res);
        }
    }
}

extern "C" void kernel_launch(void* const* d_in, const int* in_sizes, int n_in,
                              void* d_out, int out_size) {
    const int*   node_idx = (const int*)  d_in[0];   // [16, 8192]
    const int*   edge_idx = (const int*)  d_in[1];   // [15, 8192]
    const int*   val_idx  = (const int*)  d_in[2];   // [131072, 8]
    const float* val_w    = (const float*)d_in[3];   // [131072, 8]
    const float* node_tab = (const float*)d_in[4];   // [128, 256]
    const float* edge_tab = (const float*)d_in[5];   // [32, 256]
    const float* val_tab  = (const float*)d_in[6];   // [10000, 256]
    float* out = (float*)d_out;                      // [47, 8192, 256]

    (void)in_sizes; (void)n_in; (void)out_size;

    const int prep_blocks = (CVT_HALF + 255) / 256;   // 1250
    prep_absmax_kernel<<<prep_blocks, 256>>>((const float4*)val_tab);
    prep_quant_kernel <<<prep_blocks, 256>>>((const float4*)val_tab);

    const int nblocks = (BATCH / ROWS_PER_BLOCK) * L_TOTAL;   // 512 * 47 = 24064
    embed_kernel<<<nblocks, 256>>>(node_idx, edge_idx, val_idx, val_w,
                                   (const float4*)node_tab,
                                   (const float4*)edge_tab,
                                   (float4*)out);
}